// round 9
// baseline (speedup 1.0000x reference)
#include <cuda_runtime.h>
#include <cuda_fp16.h>
#include <cuda_bf16.h>
#include <stdint.h>

#define Nn 100000
#define Ee 1600000
#define Hh 64
#define Gg 128
#define MAXD 64    // per-node CSR bucket capacity (P(deg>=64) ~ 1e-20)

struct ND { int cnt; float deg; };

// ---- device scratch ----
__device__ ND    g_nd[Nn];
__device__ int2  g_csr[Nn * MAXD + 32];   // {src, bitcast(ew)}; +32 pad for int4 lookahead
__device__ __half g_h[Nn * Hh];           // node features (fp16)
__device__ __half g_hw[Nn * Hh];          // dinv-scaled h @ W (fp16)

__global__ void k_zero() {
    int i = blockIdx.x * blockDim.x + threadIdx.x;
    if (i < Nn) { g_nd[i].cnt = 0; g_nd[i].deg = 1.0f; }
}

// fused: per-edge deg accumulation + bucket placement (single edge pass)
__global__ void k_place(const int* __restrict__ ei, const float* __restrict__ ew) {
    int e = blockIdx.x * blockDim.x + threadIdx.x;
    if (e < Ee) {
        int s = ei[e];
        int d = ei[Ee + e];
        float w = ew[e];
        atomicAdd(&g_nd[d].deg, w);
        int slot = atomicAdd(&g_nd[d].cnt, 1);
        if (slot < MAXD)
            g_csr[(d << 6) + slot] = make_int2(s, __float_as_int(w));
    }
}

// ---- layer-0 GEMM: concat(x, emb[mapping]) @ W0, epilogue scaled by dinv ----
__global__ void k_gemm0(const float* __restrict__ x, const int* __restrict__ mapping,
                        const float* __restrict__ emb, const float* __restrict__ W) {
    __shared__ float sW[64][64];
    __shared__ float sH[64][68];
    int tid = threadIdx.x;   // 256
    int rowBase = blockIdx.x * 64;
    #pragma unroll
    for (int i = 0; i < 4; i++) {
        int t = tid + i * 256;
        reinterpret_cast<float4*>(&sW[0][0])[t] = reinterpret_cast<const float4*>(W)[t];
    }
    #pragma unroll
    for (int i = 0; i < 4; i++) {
        int t = tid + i * 256;
        int r = t >> 4;
        int q = t & 15;
        int gr = rowBase + r;
        float4 v = make_float4(0.f, 0.f, 0.f, 0.f);
        if (gr < Nn) {
            if (q < 8) v = reinterpret_cast<const float4*>(x)[gr * 8 + q];
            else {
                int m = __ldg(&mapping[gr]);
                v = reinterpret_cast<const float4*>(emb)[m * 8 + (q - 8)];
            }
        }
        *reinterpret_cast<float4*>(&sH[r][q * 4]) = v;
    }
    __syncthreads();
    int cq = tid & 15;
    int rq = tid >> 4;
    float acc[4][4];
    #pragma unroll
    for (int j = 0; j < 4; j++)
        #pragma unroll
        for (int i = 0; i < 4; i++) acc[j][i] = 0.0f;
    #pragma unroll
    for (int k = 0; k < 64; k++) {
        float4 w = *reinterpret_cast<float4*>(&sW[k][cq * 4]);
        #pragma unroll
        for (int j = 0; j < 4; j++) {
            float a = sH[rq * 4 + j][k];
            acc[j][0] += a * w.x;
            acc[j][1] += a * w.y;
            acc[j][2] += a * w.z;
            acc[j][3] += a * w.w;
        }
    }
    #pragma unroll
    for (int j = 0; j < 4; j++) {
        int gr = rowBase + rq * 4 + j;
        if (gr >= Nn) continue;
        float dg = g_nd[gr].deg;
        float s = (dg > 0.f) ? rsqrtf(dg) : 0.f;
        __half2* dst = reinterpret_cast<__half2*>(&g_hw[gr * 64 + cq * 4]);
        dst[0] = __floats2half2_rn(acc[j][0] * s, acc[j][1] * s);
        dst[1] = __floats2half2_rn(acc[j][2] * s, acc[j][3] * s);
    }
}

// ---- layer-1 GEMM: g_h (fp16) @ W1, epilogue scaled by dinv ----
__global__ void k_gemm1(const float* __restrict__ W) {
    __shared__ float sW[64][64];
    __shared__ __half2 sH[64][36];
    int tid = threadIdx.x;
    int rowBase = blockIdx.x * 64;
    #pragma unroll
    for (int i = 0; i < 4; i++) {
        int t = tid + i * 256;
        reinterpret_cast<float4*>(&sW[0][0])[t] = reinterpret_cast<const float4*>(W)[t];
    }
    #pragma unroll
    for (int i = 0; i < 2; i++) {
        int t = tid + i * 256;       // 0..511
        int r = t >> 3;
        int q = t & 7;
        int gr = rowBase + r;
        uint4 v = make_uint4(0, 0, 0, 0);
        if (gr < Nn) v = reinterpret_cast<const uint4*>(g_h)[gr * 8 + q];
        *reinterpret_cast<uint4*>(&sH[r][q * 4]) = v;
    }
    __syncthreads();
    int cq = tid & 15;
    int rq = tid >> 4;
    float acc[4][4];
    #pragma unroll
    for (int j = 0; j < 4; j++)
        #pragma unroll
        for (int i = 0; i < 4; i++) acc[j][i] = 0.0f;
    #pragma unroll
    for (int k2 = 0; k2 < 32; k2++) {
        float4 w0 = *reinterpret_cast<float4*>(&sW[2 * k2][cq * 4]);
        float4 w1 = *reinterpret_cast<float4*>(&sW[2 * k2 + 1][cq * 4]);
        #pragma unroll
        for (int j = 0; j < 4; j++) {
            float2 a = __half22float2(sH[rq * 4 + j][k2]);
            acc[j][0] += a.x * w0.x + a.y * w1.x;
            acc[j][1] += a.x * w0.y + a.y * w1.y;
            acc[j][2] += a.x * w0.z + a.y * w1.z;
            acc[j][3] += a.x * w0.w + a.y * w1.w;
        }
    }
    #pragma unroll
    for (int j = 0; j < 4; j++) {
        int gr = rowBase + rq * 4 + j;
        if (gr >= Nn) continue;
        float dg = g_nd[gr].deg;
        float s = (dg > 0.f) ? rsqrtf(dg) : 0.f;
        __half2* dst = reinterpret_cast<__half2*>(&g_hw[gr * 64 + cq * 4]);
        dst[0] = __floats2half2_rn(acc[j][0] * s, acc[j][1] * s);
        dst[1] = __floats2half2_rn(acc[j][2] * s, acc[j][3] * s);
    }
}

// per-edge accumulate with validity predication (warp-uniform)
__device__ __forceinline__ void edge_acc(const __half2* hw2, int lane,
                                         int src, int wbits, bool valid, float2& acc) {
    int s = valid ? src : 0;
    float w = valid ? __int_as_float(wbits) : 0.f;
    float2 v = __half22float2(hw2[s * 32 + lane]);
    acc.x += w * v.x;
    acc.y += w * v.y;
}

// gather: TWO nodes per warp, interleaved edge streams for 2x MLP
__global__ void k_gather(const float* __restrict__ b) {
    int w = blockIdx.x * 8 + (threadIdx.x >> 5);
    int n0 = w * 2;
    if (n0 >= Nn) return;
    int n1 = n0 + 1;
    bool has1 = n1 < Nn;
    int lane = threadIdx.x & 31;
    const __half2* hw2 = reinterpret_cast<const __half2*>(g_hw);

    ND nd0 = g_nd[n0];
    ND nd1 = has1 ? g_nd[n1] : nd0;
    float di0 = (nd0.deg > 0.f) ? rsqrtf(nd0.deg) : 0.f;
    float di1 = (nd1.deg > 0.f) ? rsqrtf(nd1.deg) : 0.f;
    int c0 = nd0.cnt < MAXD ? nd0.cnt : MAXD;
    int c1 = has1 ? (nd1.cnt < MAXD ? nd1.cnt : MAXD) : 0;

    float2 acc0 = __half22float2(hw2[n0 * 32 + lane]);   // self terms (dinv-scaled)
    float2 acc1 = has1 ? __half22float2(hw2[n1 * 32 + lane]) : make_float2(0.f, 0.f);

    const int4* q0 = reinterpret_cast<const int4*>(&g_csr[n0 << 6]);
    const int4* q1 = reinterpret_cast<const int4*>(&g_csr[(n1 < Nn ? n1 : n0) << 6]);
    int maxc = c0 > c1 ? c0 : c1;

    for (int e = 0; e < maxc; e += 4) {
        int4 a0, b0, a1, b1;
        bool L0 = e < c0, L1 = e < c1;
        if (L0) { a0 = __ldg(&q0[e >> 1]); b0 = __ldg(&q0[(e >> 1) + 1]); }
        else    { a0 = make_int4(0,0,0,0); b0 = a0; }
        if (L1) { a1 = __ldg(&q1[e >> 1]); b1 = __ldg(&q1[(e >> 1) + 1]); }
        else    { a1 = make_int4(0,0,0,0); b1 = a1; }
        edge_acc(hw2, lane, a0.x, a0.y, e + 0 < c0, acc0);
        edge_acc(hw2, lane, a1.x, a1.y, e + 0 < c1, acc1);
        edge_acc(hw2, lane, a0.z, a0.w, e + 1 < c0, acc0);
        edge_acc(hw2, lane, a1.z, a1.w, e + 1 < c1, acc1);
        edge_acc(hw2, lane, b0.x, b0.y, e + 2 < c0, acc0);
        edge_acc(hw2, lane, b1.x, b1.y, e + 2 < c1, acc1);
        edge_acc(hw2, lane, b0.z, b0.w, e + 3 < c0, acc0);
        edge_acc(hw2, lane, b1.z, b1.w, e + 3 < c1, acc1);
    }

    float2 bb = reinterpret_cast<const float2*>(b)[lane];
    acc0.x = fmaxf(fmaf(acc0.x, di0, bb.x), 0.f);
    acc0.y = fmaxf(fmaf(acc0.y, di0, bb.y), 0.f);
    reinterpret_cast<__half2*>(g_h)[n0 * 32 + lane] = __floats2half2_rn(acc0.x, acc0.y);
    if (has1) {
        acc1.x = fmaxf(fmaf(acc1.x, di1, bb.x), 0.f);
        acc1.y = fmaxf(fmaf(acc1.y, di1, bb.y), 0.f);
        reinterpret_cast<__half2*>(g_h)[n1 * 32 + lane] = __floats2half2_rn(acc1.x, acc1.y);
    }
}

// mean pool (batch sorted): one block per graph; h is fp16
__global__ void k_pool(const int* __restrict__ batch, float* __restrict__ out) {
    __shared__ float sh[8][64];
    int g = blockIdx.x;
    int tid = threadIdx.x;   // 256
    int lo = 0, hi = Nn;
    while (lo < hi) { int mid = (lo + hi) >> 1; if (batch[mid] < g) lo = mid + 1; else hi = mid; }
    int start = lo;
    lo = start; hi = Nn;
    while (lo < hi) { int mid = (lo + hi) >> 1; if (batch[mid] < g + 1) lo = mid + 1; else hi = mid; }
    int end = lo;
    int c2 = tid & 31;
    int r = tid >> 5;
    const __half2* h2 = reinterpret_cast<const __half2*>(g_h);
    float2 acc = make_float2(0.f, 0.f);
    for (int node = start + r; node < end; node += 8) {
        float2 v = __half22float2(h2[node * 32 + c2]);
        acc.x += v.x; acc.y += v.y;
    }
    sh[r][c2 * 2] = acc.x;
    sh[r][c2 * 2 + 1] = acc.y;
    __syncthreads();
    if (tid < 64) {
        float su = 0.f;
        #pragma unroll
        for (int k = 0; k < 8; k++) su += sh[k][tid];
        float cnt = (float)(end - start);
        out[g * 64 + tid] = su / fmaxf(cnt, 1.0f);
    }
}

extern "C" void kernel_launch(void* const* d_in, const int* in_sizes, int n_in,
                              void* d_out, int out_size) {
    const float* x       = (const float*)d_in[0];
    const int*   mapping = (const int*)d_in[1];
    const int*   ei      = (const int*)d_in[2];
    const float* ew      = (const float*)d_in[3];
    const int*   batch   = (const int*)d_in[4];
    const float* emb     = (const float*)d_in[5];
    const float* W0      = (const float*)d_in[6];
    const float* b0      = (const float*)d_in[7];
    const float* W1      = (const float*)d_in[8];
    const float* b1      = (const float*)d_in[9];
    float* out = (float*)d_out;

    const int T = 256;
    k_zero<<<(Nn + T - 1) / T, T>>>();
    k_place<<<(Ee + T - 1) / T, T>>>(ei, ew);

    k_gemm0<<<(Nn + 63) / 64, T>>>(x, mapping, emb, W0);
    int gatherBlocks = ((Nn + 1) / 2 + 7) / 8;
    k_gather<<<gatherBlocks, T>>>(b0);

    k_gemm1<<<(Nn + 63) / 64, T>>>(W1);
    k_gather<<<gatherBlocks, T>>>(b1);

    k_pool<<<Gg, T>>>(batch, out);
}

// round 10
// speedup vs baseline: 1.0198x; 1.0198x over previous
#include <cuda_runtime.h>
#include <cuda_fp16.h>
#include <cuda_bf16.h>
#include <stdint.h>

#define Nn 100000
#define Ee 1600000
#define Hh 64
#define Gg 128
#define MAXD 64    // per-node CSR bucket capacity (P(deg>=64) ~ 1e-20)

struct ND { int cnt; float deg; };

// ---- device scratch ----
__device__ ND    g_nd[Nn];
__device__ int2  g_csr[Nn * MAXD];     // {src, half2(w,w) bits}; blocks of 8 zero-padded
__device__ __half g_h[Nn * Hh];        // node features (fp16)
__device__ __half g_hw[Nn * Hh];       // dinv-scaled h @ W (fp16)

__global__ void k_zero() {
    int i = blockIdx.x * blockDim.x + threadIdx.x;
    if (i < Nn) { g_nd[i].cnt = 0; g_nd[i].deg = 1.0f; }
}

// fused: per-edge deg accumulation + bucket placement (single edge pass)
__global__ void k_place(const int* __restrict__ ei, const float* __restrict__ ew) {
    int e = blockIdx.x * blockDim.x + threadIdx.x;
    if (e < Ee) {
        int s = ei[e];
        int d = ei[Ee + e];
        float w = ew[e];
        atomicAdd(&g_nd[d].deg, w);
        int slot = atomicAdd(&g_nd[d].cnt, 1);
        if (slot < MAXD) {
            __half2 wp = __float2half2_rn(w);
            g_csr[(d << 6) + slot] = make_int2(s, *reinterpret_cast<int*>(&wp));
        }
    }
}

// zero-pad each bucket up to the next multiple of 8 (zero weight = exact no-op)
__global__ void k_pad() {
    int n = blockIdx.x * blockDim.x + threadIdx.x;
    if (n < Nn) {
        int c = g_nd[n].cnt;
        if (c > MAXD) c = MAXD;
        int r = (c + 7) & ~7;
        for (int s = c; s < r; s++)
            g_csr[(n << 6) + s] = make_int2(0, 0);
    }
}

// ---- layer-0 GEMM: concat(x, emb[mapping]) @ W0, epilogue scaled by dinv ----
__global__ void k_gemm0(const float* __restrict__ x, const int* __restrict__ mapping,
                        const float* __restrict__ emb, const float* __restrict__ W) {
    __shared__ float sW[64][64];
    __shared__ float sH[64][68];
    int tid = threadIdx.x;   // 256
    int rowBase = blockIdx.x * 64;
    #pragma unroll
    for (int i = 0; i < 4; i++) {
        int t = tid + i * 256;
        reinterpret_cast<float4*>(&sW[0][0])[t] = reinterpret_cast<const float4*>(W)[t];
    }
    #pragma unroll
    for (int i = 0; i < 4; i++) {
        int t = tid + i * 256;
        int r = t >> 4;
        int q = t & 15;
        int gr = rowBase + r;
        float4 v = make_float4(0.f, 0.f, 0.f, 0.f);
        if (gr < Nn) {
            if (q < 8) v = reinterpret_cast<const float4*>(x)[gr * 8 + q];
            else {
                int m = __ldg(&mapping[gr]);
                v = reinterpret_cast<const float4*>(emb)[m * 8 + (q - 8)];
            }
        }
        *reinterpret_cast<float4*>(&sH[r][q * 4]) = v;
    }
    __syncthreads();
    int cq = tid & 15;
    int rq = tid >> 4;
    float acc[4][4];
    #pragma unroll
    for (int j = 0; j < 4; j++)
        #pragma unroll
        for (int i = 0; i < 4; i++) acc[j][i] = 0.0f;
    #pragma unroll
    for (int k = 0; k < 64; k++) {
        float4 w = *reinterpret_cast<float4*>(&sW[k][cq * 4]);
        #pragma unroll
        for (int j = 0; j < 4; j++) {
            float a = sH[rq * 4 + j][k];
            acc[j][0] += a * w.x;
            acc[j][1] += a * w.y;
            acc[j][2] += a * w.z;
            acc[j][3] += a * w.w;
        }
    }
    #pragma unroll
    for (int j = 0; j < 4; j++) {
        int gr = rowBase + rq * 4 + j;
        if (gr >= Nn) continue;
        float dg = g_nd[gr].deg;
        float s = (dg > 0.f) ? rsqrtf(dg) : 0.f;
        __half2* dst = reinterpret_cast<__half2*>(&g_hw[gr * 64 + cq * 4]);
        dst[0] = __floats2half2_rn(acc[j][0] * s, acc[j][1] * s);
        dst[1] = __floats2half2_rn(acc[j][2] * s, acc[j][3] * s);
    }
}

// ---- layer-1 GEMM: g_h (fp16) @ W1, epilogue scaled by dinv ----
__global__ void k_gemm1(const float* __restrict__ W) {
    __shared__ float sW[64][64];
    __shared__ __half2 sH[64][36];
    int tid = threadIdx.x;
    int rowBase = blockIdx.x * 64;
    #pragma unroll
    for (int i = 0; i < 4; i++) {
        int t = tid + i * 256;
        reinterpret_cast<float4*>(&sW[0][0])[t] = reinterpret_cast<const float4*>(W)[t];
    }
    #pragma unroll
    for (int i = 0; i < 2; i++) {
        int t = tid + i * 256;       // 0..511
        int r = t >> 3;
        int q = t & 7;
        int gr = rowBase + r;
        uint4 v = make_uint4(0, 0, 0, 0);
        if (gr < Nn) v = reinterpret_cast<const uint4*>(g_h)[gr * 8 + q];
        *reinterpret_cast<uint4*>(&sH[r][q * 4]) = v;
    }
    __syncthreads();
    int cq = tid & 15;
    int rq = tid >> 4;
    float acc[4][4];
    #pragma unroll
    for (int j = 0; j < 4; j++)
        #pragma unroll
        for (int i = 0; i < 4; i++) acc[j][i] = 0.0f;
    #pragma unroll
    for (int k2 = 0; k2 < 32; k2++) {
        float4 w0 = *reinterpret_cast<float4*>(&sW[2 * k2][cq * 4]);
        float4 w1 = *reinterpret_cast<float4*>(&sW[2 * k2 + 1][cq * 4]);
        #pragma unroll
        for (int j = 0; j < 4; j++) {
            float2 a = __half22float2(sH[rq * 4 + j][k2]);
            acc[j][0] += a.x * w0.x + a.y * w1.x;
            acc[j][1] += a.x * w0.y + a.y * w1.y;
            acc[j][2] += a.x * w0.z + a.y * w1.z;
            acc[j][3] += a.x * w0.w + a.y * w1.w;
        }
    }
    #pragma unroll
    for (int j = 0; j < 4; j++) {
        int gr = rowBase + rq * 4 + j;
        if (gr >= Nn) continue;
        float dg = g_nd[gr].deg;
        float s = (dg > 0.f) ? rsqrtf(dg) : 0.f;
        __half2* dst = reinterpret_cast<__half2*>(&g_hw[gr * 64 + cq * 4]);
        dst[0] = __floats2half2_rn(acc[j][0] * s, acc[j][1] * s);
        dst[1] = __floats2half2_rn(acc[j][2] * s, acc[j][3] * s);
    }
}

// one unpredicated 8-edge block: fp16 dual-chain accumulate, fold into fp32 acc
__device__ __forceinline__ void block8(const int4* q, const __half2* hw2,
                                       int lane, float2& accf) {
    int4 a = __ldg(&q[0]);
    int4 b = __ldg(&q[1]);
    int4 c = __ldg(&q[2]);
    int4 d = __ldg(&q[3]);
    __half2 v0 = hw2[a.x * 32 + lane];
    __half2 v1 = hw2[a.z * 32 + lane];
    __half2 v2 = hw2[b.x * 32 + lane];
    __half2 v3 = hw2[b.z * 32 + lane];
    __half2 v4 = hw2[c.x * 32 + lane];
    __half2 v5 = hw2[c.z * 32 + lane];
    __half2 v6 = hw2[d.x * 32 + lane];
    __half2 v7 = hw2[d.z * 32 + lane];
    __half2 s0 = __hmul2(v0, *reinterpret_cast<__half2*>(&a.y));
    __half2 s1 = __hmul2(v1, *reinterpret_cast<__half2*>(&a.w));
    s0 = __hfma2(v2, *reinterpret_cast<__half2*>(&b.y), s0);
    s1 = __hfma2(v3, *reinterpret_cast<__half2*>(&b.w), s1);
    s0 = __hfma2(v4, *reinterpret_cast<__half2*>(&c.y), s0);
    s1 = __hfma2(v5, *reinterpret_cast<__half2*>(&c.w), s1);
    s0 = __hfma2(v6, *reinterpret_cast<__half2*>(&d.y), s0);
    s1 = __hfma2(v7, *reinterpret_cast<__half2*>(&d.w), s1);
    float2 p0 = __half22float2(s0);
    float2 p1 = __half22float2(s1);
    accf.x += p0.x + p1.x;
    accf.y += p0.y + p1.y;
}

// gather: TWO nodes per warp, unpredicated 8-edge blocks (zero-padded buckets)
__global__ void k_gather(const float* __restrict__ b) {
    int w = blockIdx.x * 8 + (threadIdx.x >> 5);
    int n0 = w * 2;
    if (n0 >= Nn) return;
    int n1 = n0 + 1;
    bool has1 = n1 < Nn;
    int lane = threadIdx.x & 31;
    const __half2* hw2 = reinterpret_cast<const __half2*>(g_hw);

    ND nd0 = g_nd[n0];
    ND nd1 = has1 ? g_nd[n1] : nd0;
    float di0 = (nd0.deg > 0.f) ? rsqrtf(nd0.deg) : 0.f;
    float di1 = (nd1.deg > 0.f) ? rsqrtf(nd1.deg) : 0.f;
    int c0 = nd0.cnt < MAXD ? nd0.cnt : MAXD;
    int c1 = has1 ? (nd1.cnt < MAXD ? nd1.cnt : MAXD) : 0;
    int nb0 = (c0 + 7) >> 3;
    int nb1 = (c1 + 7) >> 3;

    float2 acc0 = __half22float2(hw2[n0 * 32 + lane]);   // self terms (dinv-scaled)
    float2 acc1 = has1 ? __half22float2(hw2[n1 * 32 + lane]) : make_float2(0.f, 0.f);

    const int4* q0 = reinterpret_cast<const int4*>(&g_csr[n0 << 6]);
    const int4* q1 = reinterpret_cast<const int4*>(&g_csr[(has1 ? n1 : n0) << 6]);
    int maxb = nb0 > nb1 ? nb0 : nb1;

    for (int ib = 0; ib < maxb; ib++) {
        if (ib < nb0) block8(q0 + ib * 4, hw2, lane, acc0);
        if (ib < nb1) block8(q1 + ib * 4, hw2, lane, acc1);
    }

    float2 bb = reinterpret_cast<const float2*>(b)[lane];
    acc0.x = fmaxf(fmaf(acc0.x, di0, bb.x), 0.f);
    acc0.y = fmaxf(fmaf(acc0.y, di0, bb.y), 0.f);
    reinterpret_cast<__half2*>(g_h)[n0 * 32 + lane] = __floats2half2_rn(acc0.x, acc0.y);
    if (has1) {
        acc1.x = fmaxf(fmaf(acc1.x, di1, bb.x), 0.f);
        acc1.y = fmaxf(fmaf(acc1.y, di1, bb.y), 0.f);
        reinterpret_cast<__half2*>(g_h)[n1 * 32 + lane] = __floats2half2_rn(acc1.x, acc1.y);
    }
}

// mean pool (batch sorted): one block per graph; h is fp16
__global__ void k_pool(const int* __restrict__ batch, float* __restrict__ out) {
    __shared__ float sh[8][64];
    int g = blockIdx.x;
    int tid = threadIdx.x;   // 256
    int lo = 0, hi = Nn;
    while (lo < hi) { int mid = (lo + hi) >> 1; if (batch[mid] < g) lo = mid + 1; else hi = mid; }
    int start = lo;
    lo = start; hi = Nn;
    while (lo < hi) { int mid = (lo + hi) >> 1; if (batch[mid] < g + 1) lo = mid + 1; else hi = mid; }
    int end = lo;
    int c2 = tid & 31;
    int r = tid >> 5;
    const __half2* h2 = reinterpret_cast<const __half2*>(g_h);
    float2 acc = make_float2(0.f, 0.f);
    for (int node = start + r; node < end; node += 8) {
        float2 v = __half22float2(h2[node * 32 + c2]);
        acc.x += v.x; acc.y += v.y;
    }
    sh[r][c2 * 2] = acc.x;
    sh[r][c2 * 2 + 1] = acc.y;
    __syncthreads();
    if (tid < 64) {
        float su = 0.f;
        #pragma unroll
        for (int k = 0; k < 8; k++) su += sh[k][tid];
        float cnt = (float)(end - start);
        out[g * 64 + tid] = su / fmaxf(cnt, 1.0f);
    }
}

extern "C" void kernel_launch(void* const* d_in, const int* in_sizes, int n_in,
                              void* d_out, int out_size) {
    const float* x       = (const float*)d_in[0];
    const int*   mapping = (const int*)d_in[1];
    const int*   ei      = (const int*)d_in[2];
    const float* ew      = (const float*)d_in[3];
    const int*   batch   = (const int*)d_in[4];
    const float* emb     = (const float*)d_in[5];
    const float* W0      = (const float*)d_in[6];
    const float* b0      = (const float*)d_in[7];
    const float* W1      = (const float*)d_in[8];
    const float* b1      = (const float*)d_in[9];
    float* out = (float*)d_out;

    const int T = 256;
    k_zero<<<(Nn + T - 1) / T, T>>>();
    k_place<<<(Ee + T - 1) / T, T>>>(ei, ew);
    k_pad<<<(Nn + T - 1) / T, T>>>();

    k_gemm0<<<(Nn + 63) / 64, T>>>(x, mapping, emb, W0);
    int gatherBlocks = ((Nn + 1) / 2 + 7) / 8;
    k_gather<<<gatherBlocks, T>>>(b0);

    k_gemm1<<<(Nn + 63) / 64, T>>>(W1);
    k_gather<<<gatherBlocks, T>>>(b1);

    k_pool<<<Gg, T>>>(batch, out);
}

// round 11
// speedup vs baseline: 1.1884x; 1.1653x over previous
#include <cuda_runtime.h>
#include <cuda_fp16.h>
#include <cuda_bf16.h>
#include <stdint.h>

#define Nn 100000
#define Ee 1600000
#define Hh 64
#define Gg 128
#define MAXD 64    // per-node CSR bucket capacity (P(deg>=64) ~ 1e-20)

struct ND { int cnt; float deg; };

// ---- device scratch ----
__device__ ND    g_nd[Nn];
__device__ int2  g_csr[Nn * MAXD];     // {src, bitcast(ew)} per dst bucket
__device__ __half g_h[Nn * Hh];        // node features (fp16)
__device__ __half g_hw[Nn * Hh];       // dinv-scaled h @ W (fp16)

__global__ void k_zero() {
    int i = blockIdx.x * blockDim.x + threadIdx.x;
    if (i < Nn) { g_nd[i].cnt = 0; g_nd[i].deg = 1.0f; }
}

// fused: per-edge deg accumulation + bucket placement (single edge pass)
__global__ void k_place(const int* __restrict__ ei, const float* __restrict__ ew) {
    int e = blockIdx.x * blockDim.x + threadIdx.x;
    if (e < Ee) {
        int s = ei[e];
        int d = ei[Ee + e];
        float w = ew[e];
        atomicAdd(&g_nd[d].deg, w);
        int slot = atomicAdd(&g_nd[d].cnt, 1);
        if (slot < MAXD)
            g_csr[(d << 6) + slot] = make_int2(s, __float_as_int(w));
    }
}

// ---- HMMA m16n8k16 wrapper ----
__device__ __forceinline__ void mma16816(float& d0, float& d1, float& d2, float& d3,
                                         uint32_t a0, uint32_t a1, uint32_t a2, uint32_t a3,
                                         uint32_t b0, uint32_t b1) {
    asm volatile(
        "mma.sync.aligned.m16n8k16.row.col.f32.f16.f16.f32 "
        "{%0,%1,%2,%3}, {%4,%5,%6,%7}, {%8,%9}, {%0,%1,%2,%3};\n"
        : "+f"(d0), "+f"(d1), "+f"(d2), "+f"(d3)
        : "r"(a0), "r"(a1), "r"(a2), "r"(a3), "r"(b0), "r"(b1));
}

// shared compute: sA[128][72] fp16 rows, sWT[64][72] fp16 (n-major W^T)
// 8 warps x 16 rows; output g_hw scaled by dinv
__device__ __forceinline__ void gemm_mma_compute(const __half (*sA)[72], const __half (*sWT)[72],
                                                 int rowBase, int tid) {
    int wid = tid >> 5;
    int lane = tid & 31;
    int gid = lane >> 2;        // groupID 0..7
    int tg = lane & 3;          // thread in group
    int r0 = wid * 16 + gid;    // local row (and +8)

    float c[8][4];
    #pragma unroll
    for (int nt = 0; nt < 8; nt++)
        #pragma unroll
        for (int i = 0; i < 4; i++) c[nt][i] = 0.f;

    #pragma unroll
    for (int kc = 0; kc < 4; kc++) {
        int kb = kc * 16 + tg * 2;
        uint32_t a0 = *reinterpret_cast<const uint32_t*>(&sA[r0][kb]);
        uint32_t a1 = *reinterpret_cast<const uint32_t*>(&sA[r0 + 8][kb]);
        uint32_t a2 = *reinterpret_cast<const uint32_t*>(&sA[r0][kb + 8]);
        uint32_t a3 = *reinterpret_cast<const uint32_t*>(&sA[r0 + 8][kb + 8]);
        #pragma unroll
        for (int nt = 0; nt < 8; nt++) {
            uint32_t b0 = *reinterpret_cast<const uint32_t*>(&sWT[nt * 8 + gid][kb]);
            uint32_t b1 = *reinterpret_cast<const uint32_t*>(&sWT[nt * 8 + gid][kb + 8]);
            mma16816(c[nt][0], c[nt][1], c[nt][2], c[nt][3], a0, a1, a2, a3, b0, b1);
        }
    }

    int gr0 = rowBase + r0;
    int gr1 = gr0 + 8;
    float dg0 = g_nd[gr0 < Nn ? gr0 : 0].deg;
    float dg1 = g_nd[gr1 < Nn ? gr1 : 0].deg;
    float s0 = (dg0 > 0.f) ? rsqrtf(dg0) : 0.f;
    float s1 = (dg1 > 0.f) ? rsqrtf(dg1) : 0.f;
    #pragma unroll
    for (int nt = 0; nt < 8; nt++) {
        int col = nt * 8 + tg * 2;
        if (gr0 < Nn)
            *reinterpret_cast<__half2*>(&g_hw[gr0 * 64 + col]) =
                __floats2half2_rn(c[nt][0] * s0, c[nt][1] * s0);
        if (gr1 < Nn)
            *reinterpret_cast<__half2*>(&g_hw[gr1 * 64 + col]) =
                __floats2half2_rn(c[nt][2] * s1, c[nt][3] * s1);
    }
}

// ---- layer-0 GEMM (tensor core): concat(x, emb[mapping]) @ W0 ----
__global__ void k_gemm0(const float* __restrict__ x, const int* __restrict__ mapping,
                        const float* __restrict__ emb, const float* __restrict__ W) {
    __shared__ __half sA[128][72];
    __shared__ __half sWT[64][72];
    int tid = threadIdx.x;   // 256
    int rowBase = blockIdx.x * 128;

    // W^T fill: sWT[n][k] = W[k*64+n]
    for (int idx = tid; idx < 4096; idx += 256) {
        int k = idx >> 6, n = idx & 63;
        sWT[n][k] = __float2half(W[idx]);
    }
    // A fill: 128 rows x 16 float4 chunks
    #pragma unroll
    for (int i = 0; i < 8; i++) {
        int t = tid + i * 256;         // 0..2047
        int r = t >> 4;
        int q = t & 15;
        int gr = rowBase + r;
        float4 v = make_float4(0.f, 0.f, 0.f, 0.f);
        if (gr < Nn) {
            if (q < 8) v = reinterpret_cast<const float4*>(x)[gr * 8 + q];
            else {
                int m = __ldg(&mapping[gr]);
                v = reinterpret_cast<const float4*>(emb)[m * 8 + (q - 8)];
            }
        }
        __half2 p0 = __floats2half2_rn(v.x, v.y);
        __half2 p1 = __floats2half2_rn(v.z, v.w);
        uint2 pk = make_uint2(*reinterpret_cast<uint32_t*>(&p0), *reinterpret_cast<uint32_t*>(&p1));
        *reinterpret_cast<uint2*>(&sA[r][q * 4]) = pk;
    }
    __syncthreads();
    gemm_mma_compute(sA, sWT, rowBase, tid);
}

// ---- layer-1 GEMM (tensor core): g_h (fp16) @ W1 ----
__global__ void k_gemm1(const float* __restrict__ W) {
    __shared__ __half sA[128][72];
    __shared__ __half sWT[64][72];
    int tid = threadIdx.x;
    int rowBase = blockIdx.x * 128;

    for (int idx = tid; idx < 4096; idx += 256) {
        int k = idx >> 6, n = idx & 63;
        sWT[n][k] = __float2half(W[idx]);
    }
    #pragma unroll
    for (int i = 0; i < 4; i++) {
        int t = tid + i * 256;         // 0..1023
        int r = t >> 3;
        int q = t & 7;
        int gr = rowBase + r;
        uint4 v = make_uint4(0, 0, 0, 0);
        if (gr < Nn) v = reinterpret_cast<const uint4*>(g_h)[gr * 8 + q];
        *reinterpret_cast<uint4*>(&sA[r][q * 8]) = v;
    }
    __syncthreads();
    gemm_mma_compute(sA, sWT, rowBase, tid);
}

// gather (R7-proven): one warp per node, fp32 accumulation, 4-edge unroll
__device__ __forceinline__ float2 gather_core(int n, int lane, float* dinv_out) {
    const __half2* hw2 = reinterpret_cast<const __half2*>(g_hw);
    ND nd = g_nd[n];
    *dinv_out = (nd.deg > 0.f) ? rsqrtf(nd.deg) : 0.f;
    int cnt = nd.cnt < MAXD ? nd.cnt : MAXD;
    float2 acc = __half22float2(hw2[n * 32 + lane]);   // self term (dinv-scaled)
    const int4* csr4 = reinterpret_cast<const int4*>(&g_csr[n << 6]);
    int e = 0;
    for (; e + 3 < cnt; e += 4) {
        int4 p0 = __ldg(&csr4[e >> 1]);
        int4 p1 = __ldg(&csr4[(e >> 1) + 1]);
        float2 v0 = __half22float2(hw2[p0.x * 32 + lane]);
        float2 v1 = __half22float2(hw2[p0.z * 32 + lane]);
        float2 v2 = __half22float2(hw2[p1.x * 32 + lane]);
        float2 v3 = __half22float2(hw2[p1.z * 32 + lane]);
        float w0 = __int_as_float(p0.y), w1 = __int_as_float(p0.w);
        float w2 = __int_as_float(p1.y), w3 = __int_as_float(p1.w);
        acc.x += w0 * v0.x + w1 * v1.x + w2 * v2.x + w3 * v3.x;
        acc.y += w0 * v0.y + w1 * v1.y + w2 * v2.y + w3 * v3.y;
    }
    const int2* csr = &g_csr[n << 6];
    for (; e < cnt; e++) {
        int2 sw = __ldg(&csr[e]);
        float w = __int_as_float(sw.y);
        float2 v = __half22float2(hw2[sw.x * 32 + lane]);
        acc.x += w * v.x;
        acc.y += w * v.y;
    }
    return acc;
}

__global__ void k_gather(const float* __restrict__ b) {
    int n = blockIdx.x * 8 + (threadIdx.x >> 5);
    if (n >= Nn) return;
    int lane = threadIdx.x & 31;
    float dinv;
    float2 acc = gather_core(n, lane, &dinv);
    float2 bb = reinterpret_cast<const float2*>(b)[lane];
    acc.x = fmaxf(fmaf(acc.x, dinv, bb.x), 0.f);
    acc.y = fmaxf(fmaf(acc.y, dinv, bb.y), 0.f);
    reinterpret_cast<__half2*>(g_h)[n * 32 + lane] = __floats2half2_rn(acc.x, acc.y);
}

// mean pool (batch sorted): one block per graph; h is fp16
__global__ void k_pool(const int* __restrict__ batch, float* __restrict__ out) {
    __shared__ float sh[8][64];
    int g = blockIdx.x;
    int tid = threadIdx.x;   // 256
    int lo = 0, hi = Nn;
    while (lo < hi) { int mid = (lo + hi) >> 1; if (batch[mid] < g) lo = mid + 1; else hi = mid; }
    int start = lo;
    lo = start; hi = Nn;
    while (lo < hi) { int mid = (lo + hi) >> 1; if (batch[mid] < g + 1) lo = mid + 1; else hi = mid; }
    int end = lo;
    int c2 = tid & 31;
    int r = tid >> 5;
    const __half2* h2 = reinterpret_cast<const __half2*>(g_h);
    float2 acc = make_float2(0.f, 0.f);
    for (int node = start + r; node < end; node += 8) {
        float2 v = __half22float2(h2[node * 32 + c2]);
        acc.x += v.x; acc.y += v.y;
    }
    sh[r][c2 * 2] = acc.x;
    sh[r][c2 * 2 + 1] = acc.y;
    __syncthreads();
    if (tid < 64) {
        float su = 0.f;
        #pragma unroll
        for (int k = 0; k < 8; k++) su += sh[k][tid];
        float cnt = (float)(end - start);
        out[g * 64 + tid] = su / fmaxf(cnt, 1.0f);
    }
}

extern "C" void kernel_launch(void* const* d_in, const int* in_sizes, int n_in,
                              void* d_out, int out_size) {
    const float* x       = (const float*)d_in[0];
    const int*   mapping = (const int*)d_in[1];
    const int*   ei      = (const int*)d_in[2];
    const float* ew      = (const float*)d_in[3];
    const int*   batch   = (const int*)d_in[4];
    const float* emb     = (const float*)d_in[5];
    const float* W0      = (const float*)d_in[6];
    const float* b0      = (const float*)d_in[7];
    const float* W1      = (const float*)d_in[8];
    const float* b1      = (const float*)d_in[9];
    float* out = (float*)d_out;

    const int T = 256;
    k_zero<<<(Nn + T - 1) / T, T>>>();
    k_place<<<(Ee + T - 1) / T, T>>>(ei, ew);

    int gemmBlocks = (Nn + 127) / 128;
    k_gemm0<<<gemmBlocks, T>>>(x, mapping, emb, W0);
    k_gather<<<(Nn + 7) / 8, T>>>(b0);

    k_gemm1<<<gemmBlocks, T>>>(W1);
    k_gather<<<(Nn + 7) / 8, T>>>(b1);

    k_pool<<<Gg, T>>>(batch, out);
}

// round 12
// speedup vs baseline: 1.2394x; 1.0429x over previous
#include <cuda_runtime.h>
#include <cuda_fp16.h>
#include <cuda_bf16.h>
#include <stdint.h>

#define Nn 100000
#define Ee 1600000
#define Hh 64
#define Gg 128
#define MAXD 64    // per-node CSR bucket capacity (P(deg>=64) ~ 1e-20)

struct ND { int cnt; float deg; };

// ---- device scratch ----
__device__ ND    g_nd[Nn];
__device__ int2  g_csr[Nn * MAXD];     // {src, half2(w,w) bits}; zero-padded to mult of 8
__device__ __half g_h[Nn * Hh];        // node features (fp16)
__device__ __half g_hw[Nn * Hh];       // dinv-scaled h @ W (fp16)

__global__ void k_zero() {
    int i = blockIdx.x * blockDim.x + threadIdx.x;
    if (i < Nn) { g_nd[i].cnt = 0; g_nd[i].deg = 1.0f; }
}

// fused: per-edge deg accumulation + bucket placement (single edge pass)
__global__ void k_place(const int* __restrict__ ei, const float* __restrict__ ew) {
    int e = blockIdx.x * blockDim.x + threadIdx.x;
    if (e < Ee) {
        int s = ei[e];
        int d = ei[Ee + e];
        float w = ew[e];
        atomicAdd(&g_nd[d].deg, w);
        int slot = atomicAdd(&g_nd[d].cnt, 1);
        if (slot < MAXD) {
            __half2 wp = __float2half2_rn(w);
            g_csr[(d << 6) + slot] = make_int2(s, *reinterpret_cast<int*>(&wp));
        }
    }
}

// zero-pad each bucket up to the next multiple of 8 (zero weight = exact no-op)
__global__ void k_pad() {
    int n = blockIdx.x * blockDim.x + threadIdx.x;
    if (n < Nn) {
        int c = g_nd[n].cnt;
        if (c > MAXD) c = MAXD;
        int r = (c + 7) & ~7;
        for (int s = c; s < r; s++)
            g_csr[(n << 6) + s] = make_int2(0, 0);
    }
}

// ---- HMMA m16n8k16 wrapper ----
__device__ __forceinline__ void mma16816(float& d0, float& d1, float& d2, float& d3,
                                         uint32_t a0, uint32_t a1, uint32_t a2, uint32_t a3,
                                         uint32_t b0, uint32_t b1) {
    asm volatile(
        "mma.sync.aligned.m16n8k16.row.col.f32.f16.f16.f32 "
        "{%0,%1,%2,%3}, {%4,%5,%6,%7}, {%8,%9}, {%0,%1,%2,%3};\n"
        : "+f"(d0), "+f"(d1), "+f"(d2), "+f"(d3)
        : "r"(a0), "r"(a1), "r"(a2), "r"(a3), "r"(b0), "r"(b1));
}

// shared compute: sA[128][72] fp16 rows, sWT[64][72] fp16 (n-major W^T)
__device__ __forceinline__ void gemm_mma_compute(const __half (*sA)[72], const __half (*sWT)[72],
                                                 int rowBase, int tid) {
    int wid = tid >> 5;
    int lane = tid & 31;
    int gid = lane >> 2;
    int tg = lane & 3;
    int r0 = wid * 16 + gid;

    float c[8][4];
    #pragma unroll
    for (int nt = 0; nt < 8; nt++)
        #pragma unroll
        for (int i = 0; i < 4; i++) c[nt][i] = 0.f;

    #pragma unroll
    for (int kc = 0; kc < 4; kc++) {
        int kb = kc * 16 + tg * 2;
        uint32_t a0 = *reinterpret_cast<const uint32_t*>(&sA[r0][kb]);
        uint32_t a1 = *reinterpret_cast<const uint32_t*>(&sA[r0 + 8][kb]);
        uint32_t a2 = *reinterpret_cast<const uint32_t*>(&sA[r0][kb + 8]);
        uint32_t a3 = *reinterpret_cast<const uint32_t*>(&sA[r0 + 8][kb + 8]);
        #pragma unroll
        for (int nt = 0; nt < 8; nt++) {
            uint32_t b0 = *reinterpret_cast<const uint32_t*>(&sWT[nt * 8 + gid][kb]);
            uint32_t b1 = *reinterpret_cast<const uint32_t*>(&sWT[nt * 8 + gid][kb + 8]);
            mma16816(c[nt][0], c[nt][1], c[nt][2], c[nt][3], a0, a1, a2, a3, b0, b1);
        }
    }

    int gr0 = rowBase + r0;
    int gr1 = gr0 + 8;
    float dg0 = g_nd[gr0 < Nn ? gr0 : 0].deg;
    float dg1 = g_nd[gr1 < Nn ? gr1 : 0].deg;
    float s0 = (dg0 > 0.f) ? rsqrtf(dg0) : 0.f;
    float s1 = (dg1 > 0.f) ? rsqrtf(dg1) : 0.f;
    #pragma unroll
    for (int nt = 0; nt < 8; nt++) {
        int col = nt * 8 + tg * 2;
        if (gr0 < Nn)
            *reinterpret_cast<__half2*>(&g_hw[gr0 * 64 + col]) =
                __floats2half2_rn(c[nt][0] * s0, c[nt][1] * s0);
        if (gr1 < Nn)
            *reinterpret_cast<__half2*>(&g_hw[gr1 * 64 + col]) =
                __floats2half2_rn(c[nt][2] * s1, c[nt][3] * s1);
    }
}

// ---- layer-0 GEMM (tensor core): concat(x, emb[mapping]) @ W0 ----
__global__ void k_gemm0(const float* __restrict__ x, const int* __restrict__ mapping,
                        const float* __restrict__ emb, const float* __restrict__ W) {
    __shared__ __half sA[128][72];
    __shared__ __half sWT[64][72];
    int tid = threadIdx.x;   // 256
    int rowBase = blockIdx.x * 128;

    for (int idx = tid; idx < 4096; idx += 256) {
        int k = idx >> 6, n = idx & 63;
        sWT[n][k] = __float2half(W[idx]);
    }
    #pragma unroll
    for (int i = 0; i < 8; i++) {
        int t = tid + i * 256;
        int r = t >> 4;
        int q = t & 15;
        int gr = rowBase + r;
        float4 v = make_float4(0.f, 0.f, 0.f, 0.f);
        if (gr < Nn) {
            if (q < 8) v = reinterpret_cast<const float4*>(x)[gr * 8 + q];
            else {
                int m = __ldg(&mapping[gr]);
                v = reinterpret_cast<const float4*>(emb)[m * 8 + (q - 8)];
            }
        }
        __half2 p0 = __floats2half2_rn(v.x, v.y);
        __half2 p1 = __floats2half2_rn(v.z, v.w);
        uint2 pk = make_uint2(*reinterpret_cast<uint32_t*>(&p0), *reinterpret_cast<uint32_t*>(&p1));
        *reinterpret_cast<uint2*>(&sA[r][q * 4]) = pk;
    }
    __syncthreads();
    gemm_mma_compute(sA, sWT, rowBase, tid);
}

// ---- layer-1 GEMM (tensor core): g_h (fp16) @ W1 ----
__global__ void k_gemm1(const float* __restrict__ W) {
    __shared__ __half sA[128][72];
    __shared__ __half sWT[64][72];
    int tid = threadIdx.x;
    int rowBase = blockIdx.x * 128;

    for (int idx = tid; idx < 4096; idx += 256) {
        int k = idx >> 6, n = idx & 63;
        sWT[n][k] = __float2half(W[idx]);
    }
    #pragma unroll
    for (int i = 0; i < 4; i++) {
        int t = tid + i * 256;
        int r = t >> 3;
        int q = t & 7;
        int gr = rowBase + r;
        uint4 v = make_uint4(0, 0, 0, 0);
        if (gr < Nn) v = reinterpret_cast<const uint4*>(g_h)[gr * 8 + q];
        *reinterpret_cast<uint4*>(&sA[r][q * 8]) = v;
    }
    __syncthreads();
    gemm_mma_compute(sA, sWT, rowBase, tid);
}

// gather: HALF-WARP per node (2 nodes/warp). Each lane covers 4 columns via LDG.64.
// 8-edge blocks, HFMA2 chains folded to fp32 per block.
__global__ void k_gather(const float* __restrict__ b) {
    int tid = threadIdx.x;          // 256
    int warp = tid >> 5;
    int lane = tid & 31;
    int half = lane >> 4;           // 0/1: which node in the warp
    int sub = lane & 15;            // 0..15: column quad
    int n = (blockIdx.x * 8 + warp) * 2 + half;   // grid 6250 * 16 = 100000 exactly

    ND nd = g_nd[n];
    float dinv = (nd.deg > 0.f) ? rsqrtf(nd.deg) : 0.f;
    int cnt = nd.cnt < MAXD ? nd.cnt : MAXD;
    int nb = (cnt + 7) >> 3;

    const char* hwb = reinterpret_cast<const char*>(g_hw);
    int coff = sub * 8;             // byte offset of this lane's 4 halfs within a row

    // self term (dinv-scaled)
    uint2 sv = __ldg(reinterpret_cast<const uint2*>(hwb + n * 128 + coff));
    float2 accA = __half22float2(*reinterpret_cast<__half2*>(&sv.x));
    float2 accB = __half22float2(*reinterpret_cast<__half2*>(&sv.y));

    const int4* q = reinterpret_cast<const int4*>(&g_csr[n << 6]);

    for (int ib = 0; ib < nb; ib++) {
        int4 p0 = __ldg(&q[ib * 4 + 0]);
        int4 p1 = __ldg(&q[ib * 4 + 1]);
        int4 p2 = __ldg(&q[ib * 4 + 2]);
        int4 p3 = __ldg(&q[ib * 4 + 3]);
        uint2 v0 = __ldg(reinterpret_cast<const uint2*>(hwb + p0.x * 128 + coff));
        uint2 v1 = __ldg(reinterpret_cast<const uint2*>(hwb + p0.z * 128 + coff));
        uint2 v2 = __ldg(reinterpret_cast<const uint2*>(hwb + p1.x * 128 + coff));
        uint2 v3 = __ldg(reinterpret_cast<const uint2*>(hwb + p1.z * 128 + coff));
        uint2 v4 = __ldg(reinterpret_cast<const uint2*>(hwb + p2.x * 128 + coff));
        uint2 v5 = __ldg(reinterpret_cast<const uint2*>(hwb + p2.z * 128 + coff));
        uint2 v6 = __ldg(reinterpret_cast<const uint2*>(hwb + p3.x * 128 + coff));
        uint2 v7 = __ldg(reinterpret_cast<const uint2*>(hwb + p3.z * 128 + coff));
        __half2 w0 = *reinterpret_cast<__half2*>(&p0.y);
        __half2 w1 = *reinterpret_cast<__half2*>(&p0.w);
        __half2 w2 = *reinterpret_cast<__half2*>(&p1.y);
        __half2 w3 = *reinterpret_cast<__half2*>(&p1.w);
        __half2 w4 = *reinterpret_cast<__half2*>(&p2.y);
        __half2 w5 = *reinterpret_cast<__half2*>(&p2.w);
        __half2 w6 = *reinterpret_cast<__half2*>(&p3.y);
        __half2 w7 = *reinterpret_cast<__half2*>(&p3.w);
        __half2 sA = __hmul2(*reinterpret_cast<__half2*>(&v0.x), w0);
        __half2 sB = __hmul2(*reinterpret_cast<__half2*>(&v0.y), w0);
        sA = __hfma2(*reinterpret_cast<__half2*>(&v1.x), w1, sA);
        sB = __hfma2(*reinterpret_cast<__half2*>(&v1.y), w1, sB);
        sA = __hfma2(*reinterpret_cast<__half2*>(&v2.x), w2, sA);
        sB = __hfma2(*reinterpret_cast<__half2*>(&v2.y), w2, sB);
        sA = __hfma2(*reinterpret_cast<__half2*>(&v3.x), w3, sA);
        sB = __hfma2(*reinterpret_cast<__half2*>(&v3.y), w3, sB);
        sA = __hfma2(*reinterpret_cast<__half2*>(&v4.x), w4, sA);
        sB = __hfma2(*reinterpret_cast<__half2*>(&v4.y), w4, sB);
        sA = __hfma2(*reinterpret_cast<__half2*>(&v5.x), w5, sA);
        sB = __hfma2(*reinterpret_cast<__half2*>(&v5.y), w5, sB);
        sA = __hfma2(*reinterpret_cast<__half2*>(&v6.x), w6, sA);
        sB = __hfma2(*reinterpret_cast<__half2*>(&v6.y), w6, sB);
        sA = __hfma2(*reinterpret_cast<__half2*>(&v7.x), w7, sA);
        sB = __hfma2(*reinterpret_cast<__half2*>(&v7.y), w7, sB);
        float2 fA = __half22float2(sA);
        float2 fB = __half22float2(sB);
        accA.x += fA.x; accA.y += fA.y;
        accB.x += fB.x; accB.y += fB.y;
    }

    float4 bb = reinterpret_cast<const float4*>(b)[sub];
    accA.x = fmaxf(fmaf(accA.x, dinv, bb.x), 0.f);
    accA.y = fmaxf(fmaf(accA.y, dinv, bb.y), 0.f);
    accB.x = fmaxf(fmaf(accB.x, dinv, bb.z), 0.f);
    accB.y = fmaxf(fmaf(accB.y, dinv, bb.w), 0.f);
    __half2 o0 = __floats2half2_rn(accA.x, accA.y);
    __half2 o1 = __floats2half2_rn(accB.x, accB.y);
    uint2 ov = make_uint2(*reinterpret_cast<uint32_t*>(&o0), *reinterpret_cast<uint32_t*>(&o1));
    *reinterpret_cast<uint2*>(reinterpret_cast<char*>(g_h) + n * 128 + coff) = ov;
}

// mean pool (batch sorted): one block per graph; h is fp16
__global__ void k_pool(const int* __restrict__ batch, float* __restrict__ out) {
    __shared__ float sh[8][64];
    int g = blockIdx.x;
    int tid = threadIdx.x;   // 256
    int lo = 0, hi = Nn;
    while (lo < hi) { int mid = (lo + hi) >> 1; if (batch[mid] < g) lo = mid + 1; else hi = mid; }
    int start = lo;
    lo = start; hi = Nn;
    while (lo < hi) { int mid = (lo + hi) >> 1; if (batch[mid] < g + 1) lo = mid + 1; else hi = mid; }
    int end = lo;
    int c2 = tid & 31;
    int r = tid >> 5;
    const __half2* h2 = reinterpret_cast<const __half2*>(g_h);
    float2 acc = make_float2(0.f, 0.f);
    for (int node = start + r; node < end; node += 8) {
        float2 v = __half22float2(h2[node * 32 + c2]);
        acc.x += v.x; acc.y += v.y;
    }
    sh[r][c2 * 2] = acc.x;
    sh[r][c2 * 2 + 1] = acc.y;
    __syncthreads();
    if (tid < 64) {
        float su = 0.f;
        #pragma unroll
        for (int k = 0; k < 8; k++) su += sh[k][tid];
        float cnt = (float)(end - start);
        out[g * 64 + tid] = su / fmaxf(cnt, 1.0f);
    }
}

extern "C" void kernel_launch(void* const* d_in, const int* in_sizes, int n_in,
                              void* d_out, int out_size) {
    const float* x       = (const float*)d_in[0];
    const int*   mapping = (const int*)d_in[1];
    const int*   ei      = (const int*)d_in[2];
    const float* ew      = (const float*)d_in[3];
    const int*   batch   = (const int*)d_in[4];
    const float* emb     = (const float*)d_in[5];
    const float* W0      = (const float*)d_in[6];
    const float* b0      = (const float*)d_in[7];
    const float* W1      = (const float*)d_in[8];
    const float* b1      = (const float*)d_in[9];
    float* out = (float*)d_out;

    const int T = 256;
    k_zero<<<(Nn + T - 1) / T, T>>>();
    k_place<<<(Ee + T - 1) / T, T>>>(ei, ew);
    k_pad<<<(Nn + T - 1) / T, T>>>();

    int gemmBlocks = (Nn + 127) / 128;
    int gatherBlocks = Nn / 16;            // 6250, exact
    k_gemm0<<<gemmBlocks, T>>>(x, mapping, emb, W0);
    k_gather<<<gatherBlocks, T>>>(b0);

    k_gemm1<<<gemmBlocks, T>>>(W1);
    k_gather<<<gatherBlocks, T>>>(b1);

    k_pool<<<Gg, T>>>(batch, out);
}